// round 4
// baseline (speedup 1.0000x reference)
#include <cuda_runtime.h>
#include <cstdint>

#define B_    64
#define J_    1024
#define M_    256
#define NC_   32
#define DC_   32
#define EPS_  1e-7f
#define SEG_  8

// Scratch
__device__ float g_xsump[SEG_ * B_ * M_];
__device__ float g_Wv   [B_ * NC_ * M_];
__device__ float g_cxp  [SEG_ * B_ * NC_ * M_];

// ---------- f32x2 helpers ----------
__device__ __forceinline__ unsigned long long pk2(float a, float b) {
    unsigned long long r;
    asm("mov.b64 %0, {%1,%2};" : "=l"(r) : "f"(a), "f"(b));
    return r;
}
__device__ __forceinline__ void upk2(unsigned long long v, float& a, float& b) {
    asm("mov.b64 {%0,%1}, %2;" : "=f"(a), "=f"(b) : "l"(v));
}
__device__ __forceinline__ unsigned long long ffma2(unsigned long long a,
                                                    unsigned long long b,
                                                    unsigned long long c) {
    unsigned long long d;
    asm("fma.rn.f32x2 %0, %1, %2, %3;" : "=l"(d) : "l"(a), "l"(b), "l"(c));
    return d;
}

// ---------- xsum partials ----------
__global__ void __launch_bounds__(256) k_xsum(const float* __restrict__ x) {
    int b = blockIdx.x, seg = blockIdx.y;
    int m = threadIdx.x;
    size_t base = ((size_t)b * J_ + seg * 128) * M_ + m;
    float s = 0.f;
#pragma unroll 8
    for (int j = 0; j < 128; ++j) s += x[base + (size_t)j * M_];
    g_xsump[((size_t)seg * B_ + b) * M_ + m] = s;
}

// ---------- caps: out = squash(row @ W_i); Wv = W_i @ out ----------
template <int MODE>
__global__ void __launch_bounds__(256) k_caps(const float* __restrict__ W, float* __restrict__ out) {
    __shared__ float Wsh[M_ * 33];
    __shared__ float rowsh[M_];
    __shared__ float psh[8 * 32];
    __shared__ float osh[NC_];
    int t = threadIdx.x;
    int i = blockIdx.x, bg = blockIdx.y;

#pragma unroll 4
    for (int c = 0; c < 32; ++c) {
        int lin = t + 256 * c;
        int m = lin >> 5, k = lin & 31;
        Wsh[m * 33 + k] = W[m * (NC_ * DC_) + i * DC_ + k];
    }

    for (int bb = 0; bb < 4; ++bb) {
        int b = bg * 4 + bb;
        float r = 0.f;
        if (MODE == 0) {
#pragma unroll
            for (int s = 0; s < SEG_; ++s) r += g_xsump[((size_t)s * B_ + b) * M_ + t];
        } else {
#pragma unroll
            for (int s = 0; s < SEG_; ++s)
                r += g_cxp[(((size_t)s * B_ + b) * NC_ + i) * M_ + t];
        }
        __syncthreads();
        rowsh[t] = r;
        __syncthreads();

        {
            int k = t & 31, g = t >> 5;
            float p = 0.f;
#pragma unroll 8
            for (int mm = 0; mm < 32; ++mm)
                p += rowsh[g * 32 + mm] * Wsh[(g * 32 + mm) * 33 + k];
            psh[g * 32 + k] = p;
        }
        __syncthreads();

        if (t < 32) {
            float s = 0.f;
#pragma unroll
            for (int g = 0; g < 8; ++g) s += psh[g * 32 + t];
            float v = (MODE == 0) ? s * (1.0f / 32.0f) : s;
            float sq = v * v;
#pragma unroll
            for (int off = 16; off; off >>= 1) sq += __shfl_xor_sync(0xffffffffu, sq, off);
            float o = v / sqrtf(sq + EPS_);
            osh[t] = o;
            if (MODE == 2) out[((size_t)b * NC_ + i) * DC_ + t] = o;
        }
        __syncthreads();

        if (MODE != 2) {
            float wv = 0.f;
#pragma unroll
            for (int k = 0; k < 32; ++k) wv += Wsh[t * 33 + k] * osh[k];
            g_Wv[((size_t)b * NC_ + i) * M_ + t] = wv;
        }
        __syncthreads();
    }
}

// ---------- fused routing iteration: logits + softmax + cx partials ----------
// grid (64 b, 8 seg), block 256 = 8 warps. Chunks of 32 j x full K=256.
// Warp w owns capsules i = w*4..w*4+3 for both phases.
#define WV_OFF  0
#define XS_OFF  34816            // wv: 128*34*8
#define CS_OFF  (34816 + 33024)  // xsh: 32*129*8
#define SMEM_RT (CS_OFF + 32 * 36 * 4)   // csh: 32*36*4 -> 72448 total

__global__ void __launch_bounds__(256, 2) k_route(const float* __restrict__ x) {
    extern __shared__ char dyn[];
    unsigned long long* wvU = (unsigned long long*)(dyn + WV_OFF);  // [128 m2][34 pad]
    unsigned long long* xsh = (unsigned long long*)(dyn + XS_OFF);  // [32 j][129 pad]
    float*              csh = (float*)(dyn + CS_OFF);               // [32 j][36 pad]

    int t = threadIdx.x, tx = t & 31, w = t >> 5;
    int b = blockIdx.x, seg = blockIdx.y;

    // stage Wv: g_Wv[b][i][m] -> wvU[m2*34 + i]  (conflict-free STS; gmem scattered but L2-hot)
    const float4* wv4 = (const float4*)(g_Wv + (size_t)b * NC_ * M_);
#pragma unroll
    for (int c = 0; c < 8; ++c) {
        int lin = t + 256 * c;            // 2048 float4 = 32 i x 64 mq
        int i = lin & 31, mq = lin >> 5;
        float4 v = wv4[i * 64 + mq];
        wvU[(2 * mq) * 34 + i]     = pk2(v.x, v.y);
        wvU[(2 * mq + 1) * 34 + i] = pk2(v.z, v.w);
    }

    unsigned long long acc[4][4] = {};    // cx acc [ii][mm], persists across chunks

    for (int jc = 0; jc < 4; ++jc) {
        int jb = seg * 128 + jc * 32;
        __syncthreads();
        // stage x chunk: 32 j x 256 m
#pragma unroll
        for (int c = 0; c < 8; ++c) {
            int lin = t + 256 * c;        // 2048 float4
            int j = lin >> 6, mq = lin & 63;
            float4 v = *(const float4*)(x + ((size_t)b * J_ + jb + j) * M_ + mq * 4);
            xsh[j * 129 + 2 * mq]     = pk2(v.x, v.y);
            xsh[j * 129 + 2 * mq + 1] = pk2(v.z, v.w);
        }
        __syncthreads();

        // logits: thread (j = tx, i = w*4..w*4+3), full K in-chunk
        unsigned long long lacc0 = 0, lacc1 = 0, lacc2 = 0, lacc3 = 0;
        const ulonglong2* wv2 = (const ulonglong2*)wvU;
#pragma unroll 8
        for (int m2 = 0; m2 < 128; ++m2) {
            unsigned long long xv = xsh[tx * 129 + m2];
            ulonglong2 wa = wv2[m2 * 17 + w * 2];
            ulonglong2 wb = wv2[m2 * 17 + w * 2 + 1];
            lacc0 = ffma2(xv, wa.x, lacc0);
            lacc1 = ffma2(xv, wa.y, lacc1);
            lacc2 = ffma2(xv, wb.x, lacc2);
            lacc3 = ffma2(xv, wb.y, lacc3);
        }
        float4 lg;
        { float a, q;
          upk2(lacc0, a, q); lg.x = a + q;
          upk2(lacc1, a, q); lg.y = a + q;
          upk2(lacc2, a, q); lg.z = a + q;
          upk2(lacc3, a, q); lg.w = a + q; }
        *(float4*)(csh + tx * 36 + w * 4) = lg;
        __syncthreads();

        // softmax over i per j (32 threads, one j each)
        if (t < 32) {
            float* row = csh + t * 36;
            float mx = row[0];
#pragma unroll
            for (int i = 1; i < 32; ++i) mx = fmaxf(mx, row[i]);
            float s = 0.f;
#pragma unroll
            for (int i = 0; i < 32; ++i) { float e = __expf(row[i] - mx); row[i] = e; s += e; }
            float inv = 1.0f / s;
#pragma unroll
            for (int i = 0; i < 32; ++i) row[i] *= inv;
        }
        __syncthreads();

        // cx: acc[i][m] += c[j][i] * x[j][m], same x tile from smem
#pragma unroll 4
        for (int j = 0; j < 32; ++j) {
            float4 cv = *(const float4*)(csh + j * 36 + w * 4);   // broadcast
            unsigned long long cc0 = pk2(cv.x, cv.x);
            unsigned long long cc1 = pk2(cv.y, cv.y);
            unsigned long long cc2 = pk2(cv.z, cv.z);
            unsigned long long cc3 = pk2(cv.w, cv.w);
            unsigned long long xv[4];
#pragma unroll
            for (int mm = 0; mm < 4; ++mm) xv[mm] = xsh[j * 129 + tx + 32 * mm];
#pragma unroll
            for (int mm = 0; mm < 4; ++mm) {
                acc[0][mm] = ffma2(xv[mm], cc0, acc[0][mm]);
                acc[1][mm] = ffma2(xv[mm], cc1, acc[1][mm]);
                acc[2][mm] = ffma2(xv[mm], cc2, acc[2][mm]);
                acc[3][mm] = ffma2(xv[mm], cc3, acc[3][mm]);
            }
        }
    }

    // write cx partial slab (no atomics)
#pragma unroll
    for (int ii = 0; ii < 4; ++ii)
#pragma unroll
        for (int mm = 0; mm < 4; ++mm) {
            float lo, hi; upk2(acc[ii][mm], lo, hi);
            size_t o = (((size_t)seg * B_ + b) * NC_ + w * 4 + ii) * M_ + 2 * (tx + 32 * mm);
            float2 v; v.x = lo; v.y = hi;
            *(float2*)(g_cxp + o) = v;
        }
}

extern "C" void kernel_launch(void* const* d_in, const int* in_sizes, int n_in,
                              void* d_out, int out_size) {
    const float* x = (const float*)d_in[0];
    const float* W = (const float*)d_in[1];
    if (n_in >= 2 && in_sizes[0] < in_sizes[1]) {
        const float* tmp = x; x = W; W = tmp;
    }
    float* out = (float*)d_out;

    cudaFuncSetAttribute(k_route, cudaFuncAttributeMaxDynamicSharedMemorySize, SMEM_RT);

    k_xsum<<<dim3(B_, SEG_), 256>>>(x);
    k_caps<0><<<dim3(NC_, 16), 256>>>(W, out);

    k_route<<<dim3(B_, SEG_), 256, SMEM_RT>>>(x);
    k_caps<1><<<dim3(NC_, 16), 256>>>(W, out);

    k_route<<<dim3(B_, SEG_), 256, SMEM_RT>>>(x);
    k_caps<2><<<dim3(NC_, 16), 256>>>(W, out);
}

// round 5
// speedup vs baseline: 1.0920x; 1.0920x over previous
#include <cuda_runtime.h>
#include <cstdint>

#define B_    64
#define J_    1024
#define M_    256
#define NC_   32
#define DC_   32
#define EPS_  1e-7f
#define SEG_  8

// Scratch
__device__ float g_xsump[SEG_ * B_ * M_];
__device__ float g_Wv   [B_ * NC_ * M_];
__device__ float g_c    [B_ * J_ * NC_];
__device__ float g_cxp  [SEG_ * B_ * NC_ * M_];

// ---------- f32x2 helpers ----------
__device__ __forceinline__ unsigned long long pk2(float a, float b) {
    unsigned long long r;
    asm("mov.b64 %0, {%1,%2};" : "=l"(r) : "f"(a), "f"(b));
    return r;
}
__device__ __forceinline__ void upk2(unsigned long long v, float& a, float& b) {
    asm("mov.b64 {%0,%1}, %2;" : "=f"(a), "=f"(b) : "l"(v));
}
__device__ __forceinline__ unsigned long long ffma2(unsigned long long a,
                                                    unsigned long long b,
                                                    unsigned long long c) {
    unsigned long long d;
    asm("fma.rn.f32x2 %0, %1, %2, %3;" : "=l"(d) : "l"(a), "l"(b), "l"(c));
    return d;
}

// ---------- xsum partials ----------
__global__ void __launch_bounds__(256) k_xsum(const float* __restrict__ x) {
    int b = blockIdx.x, seg = blockIdx.y;
    int m = threadIdx.x;
    size_t base = ((size_t)b * J_ + seg * 128) * M_ + m;
    float s = 0.f;
#pragma unroll 8
    for (int j = 0; j < 128; ++j) s += x[base + (size_t)j * M_];
    g_xsump[((size_t)seg * B_ + b) * M_ + m] = s;
}

// ---------- caps: out = squash(row @ W_i); Wv = W_i @ out ----------
// grid (32 i, 64 b), block 256. One (b,i) per block.
template <int MODE>
__global__ void __launch_bounds__(256) k_caps(const float* __restrict__ W, float* __restrict__ out) {
    __shared__ float Wsh[M_ * 33];
    __shared__ float rowsh[M_];
    __shared__ float psh[8 * 32];
    __shared__ float osh[NC_];
    int t = threadIdx.x;
    int i = blockIdx.x, b = blockIdx.y;

#pragma unroll
    for (int c = 0; c < 32; ++c) {
        int lin = t + 256 * c;
        int m = lin >> 5, k = lin & 31;
        Wsh[m * 33 + k] = W[m * (NC_ * DC_) + i * DC_ + k];
    }

    float r = 0.f;
    if (MODE == 0) {
#pragma unroll
        for (int s = 0; s < SEG_; ++s) r += g_xsump[((size_t)s * B_ + b) * M_ + t];
    } else {
#pragma unroll
        for (int s = 0; s < SEG_; ++s)
            r += g_cxp[(((size_t)s * B_ + b) * NC_ + i) * M_ + t];
    }
    rowsh[t] = r;
    __syncthreads();

    {   // partial dots: warp g covers m = g*32..g*32+31, lane k = output dim
        int k = t & 31, g = t >> 5;
        float p = 0.f;
#pragma unroll
        for (int mm = 0; mm < 32; ++mm)
            p += rowsh[g * 32 + mm] * Wsh[(g * 32 + mm) * 33 + k];
        psh[g * 32 + k] = p;
    }
    __syncthreads();

    if (t < 32) {
        float s = 0.f;
#pragma unroll
        for (int g = 0; g < 8; ++g) s += psh[g * 32 + t];
        float v = (MODE == 0) ? s * (1.0f / 32.0f) : s;
        float sq = v * v;
#pragma unroll
        for (int off = 16; off; off >>= 1) sq += __shfl_xor_sync(0xffffffffu, sq, off);
        float o = v / sqrtf(sq + EPS_);
        osh[t] = o;
        if (MODE == 2) out[((size_t)b * NC_ + i) * DC_ + t] = o;
    }
    __syncthreads();

    if (MODE != 2) {
        float wv = 0.f;
#pragma unroll
        for (int k = 0; k < 32; ++k) wv += Wsh[t * 33 + k] * osh[k];
        g_Wv[((size_t)b * NC_ + i) * M_ + t] = wv;
    }
}

// ---------- logits + softmax ----------
// grid (64, 8), block 256 = 8 warps. Block tile 128 j x 32 i, K=256 in 4 chunks.
// Thread tile: 4j (j = tx+32jj) x 4i (i = w*4+ii).
__global__ void __launch_bounds__(256, 3) k_logits(const float* __restrict__ x) {
    extern __shared__ char dyn[];
    ulonglong2* wvP = (ulonglong2*)dyn;                 // [64 kq][33 pad]   33792 B
    ulonglong2* xsh = (ulonglong2*)(dyn + 33792);       // [128 j][17 pad]   34816 B
    float*      b1  = (float*)(dyn + 33792);            // reuse xsh

    int t = threadIdx.x, tx = t & 31, w = t >> 5;
    int b = blockIdx.x, j0 = blockIdx.y * 128;

    // stage Wv as k-quads: wvP[kq][i] = {m=4kq..4kq+1, m=4kq+2..4kq+3} for capsule i
    const float4* wv4 = (const float4*)(g_Wv + (size_t)b * NC_ * M_);
#pragma unroll
    for (int c = 0; c < 8; ++c) {
        int lin = t + 256 * c;            // 2048 float4
        int i = lin >> 6, kq = lin & 63;
        float4 v = wv4[i * 64 + kq];
        ulonglong2 p; p.x = pk2(v.x, v.y); p.y = pk2(v.z, v.w);
        wvP[kq * 33 + i] = p;
    }

    unsigned long long acc[4][4] = {};    // [jj][ii]

    for (int kc = 0; kc < 4; ++kc) {      // K chunks of 64 floats = 16 kq
        __syncthreads();
#pragma unroll
        for (int c = 0; c < 8; ++c) {
            int lin = t + 256 * c;        // 2048 float4
            int j = lin >> 4, mq = lin & 15;
            float4 v = *(const float4*)(x + ((size_t)b * J_ + j0 + j) * M_ + kc * 64 + mq * 4);
            ulonglong2 p; p.x = pk2(v.x, v.y); p.y = pk2(v.z, v.w);
            xsh[j * 17 + mq] = p;
        }
        __syncthreads();
#pragma unroll 4
        for (int kq = 0; kq < 16; ++kq) {
            ulonglong2 xv[4], wv[4];
#pragma unroll
            for (int jj = 0; jj < 4; ++jj) xv[jj] = xsh[(tx + 32 * jj) * 17 + kq];
#pragma unroll
            for (int ii = 0; ii < 4; ++ii) wv[ii] = wvP[(kc * 16 + kq) * 33 + w * 4 + ii];
#pragma unroll
            for (int jj = 0; jj < 4; ++jj)
#pragma unroll
                for (int ii = 0; ii < 4; ++ii)
                    acc[jj][ii] = ffma2(xv[jj].y, wv[ii].y,
                                  ffma2(xv[jj].x, wv[ii].x, acc[jj][ii]));
        }
    }
    __syncthreads();                      // xsh reads done; reuse as b1
#pragma unroll
    for (int jj = 0; jj < 4; ++jj)
#pragma unroll
        for (int ii = 0; ii < 4; ++ii) {
            float lo, hi; upk2(acc[jj][ii], lo, hi);
            b1[(tx + 32 * jj) * 33 + w * 4 + ii] = lo + hi;
        }
    __syncthreads();

    if (t < 128) {                        // softmax over i per j
        float* row = b1 + t * 33;
        float mx = row[0];
#pragma unroll
        for (int i = 1; i < 32; ++i) mx = fmaxf(mx, row[i]);
        float s = 0.f;
#pragma unroll
        for (int i = 0; i < 32; ++i) { float e = __expf(row[i] - mx); row[i] = e; s += e; }
        float inv = 1.0f / s;
        float* cg = g_c + ((size_t)b * J_ + j0 + t) * NC_;
#pragma unroll
        for (int q = 0; q < 8; ++q) {
            float4 o;
            o.x = row[4 * q + 0] * inv; o.y = row[4 * q + 1] * inv;
            o.z = row[4 * q + 2] * inv; o.w = row[4 * q + 3] * inv;
            ((float4*)cg)[q] = o;
        }
    }
}

// ---------- cx partials ----------
// grid (64, 8), block 256 = 8 warps. Thread tile 4i (i = w*4+ii) x 4m2 (m2 = tx+32mm).
__global__ void __launch_bounds__(256) k_cx(const float* __restrict__ x) {
    __shared__ ulonglong2 xsh[32 * 64];   // [32 j][64 ull2 = 128 m2]  32 KB
    __shared__ float      csh[32 * 32];   // [32 j][32 i]               4 KB
    int t = threadIdx.x, tx = t & 31, w = t >> 5;
    int b = blockIdx.x, seg = blockIdx.y, j0 = seg * 128;

    const unsigned long long* xshu = (const unsigned long long*)xsh;
    const float4* csh4 = (const float4*)csh;

    unsigned long long acc[4][4] = {};    // [ii][mm]

    for (int jc = 0; jc < 4; ++jc) {
        __syncthreads();
        int jb = j0 + jc * 32;
#pragma unroll
        for (int c = 0; c < 8; ++c) {
            int lin = t + 256 * c;        // 2048 float4
            int j = lin >> 6, mq = lin & 63;
            float4 v = *(const float4*)(x + ((size_t)b * J_ + jb + j) * M_ + mq * 4);
            ulonglong2 p; p.x = pk2(v.x, v.y); p.y = pk2(v.z, v.w);
            xsh[j * 64 + mq] = p;
        }
        {
            int j = t >> 3, q = t & 7;    // 256 float4 = full c tile
            float4 v = *(const float4*)(g_c + ((size_t)b * J_ + jb + j) * NC_ + q * 4);
            ((float4*)csh)[j * 8 + q] = v;
        }
        __syncthreads();
#pragma unroll 4
        for (int j = 0; j < 32; ++j) {
            float4 cv = csh4[j * 8 + w];  // broadcast: capsules w*4..w*4+3
            unsigned long long cc0 = pk2(cv.x, cv.x);
            unsigned long long cc1 = pk2(cv.y, cv.y);
            unsigned long long cc2 = pk2(cv.z, cv.z);
            unsigned long long cc3 = pk2(cv.w, cv.w);
            unsigned long long xv[4];
#pragma unroll
            for (int mm = 0; mm < 4; ++mm) xv[mm] = xshu[j * 128 + tx + 32 * mm];
#pragma unroll
            for (int mm = 0; mm < 4; ++mm) {
                acc[0][mm] = ffma2(xv[mm], cc0, acc[0][mm]);
                acc[1][mm] = ffma2(xv[mm], cc1, acc[1][mm]);
                acc[2][mm] = ffma2(xv[mm], cc2, acc[2][mm]);
                acc[3][mm] = ffma2(xv[mm], cc3, acc[3][mm]);
            }
        }
    }

#pragma unroll
    for (int ii = 0; ii < 4; ++ii)
#pragma unroll
        for (int mm = 0; mm < 4; ++mm) {
            float lo, hi; upk2(acc[ii][mm], lo, hi);
            size_t o = (((size_t)seg * B_ + b) * NC_ + w * 4 + ii) * M_ + 2 * (tx + 32 * mm);
            float2 v; v.x = lo; v.y = hi;
            *(float2*)(g_cxp + o) = v;
        }
}

extern "C" void kernel_launch(void* const* d_in, const int* in_sizes, int n_in,
                              void* d_out, int out_size) {
    const float* x = (const float*)d_in[0];
    const float* W = (const float*)d_in[1];
    if (n_in >= 2 && in_sizes[0] < in_sizes[1]) {
        const float* tmp = x; x = W; W = tmp;
    }
    float* out = (float*)d_out;

    cudaFuncSetAttribute(k_logits, cudaFuncAttributeMaxDynamicSharedMemorySize, 68608);

    k_xsum<<<dim3(B_, SEG_), 256>>>(x);
    k_caps<0><<<dim3(NC_, B_), 256>>>(W, out);

    k_logits<<<dim3(B_, SEG_), 256, 68608>>>(x);
    k_cx<<<dim3(B_, SEG_), 256>>>(x);
    k_caps<1><<<dim3(NC_, B_), 256>>>(W, out);

    k_logits<<<dim3(B_, SEG_), 256, 68608>>>(x);
    k_cx<<<dim3(B_, SEG_), 256>>>(x);
    k_caps<2><<<dim3(NC_, B_), 256>>>(W, out);
}

// round 6
// speedup vs baseline: 1.1182x; 1.0240x over previous
#include <cuda_runtime.h>
#include <cstdint>

#define B_    64
#define J_    1024
#define M_    256
#define NC_   32
#define DC_   32
#define EPS_  1e-7f
#define SEG_  8

// Scratch
__device__ float g_xsump[SEG_ * B_ * M_];
__device__ float g_Wv   [B_ * NC_ * M_];
__device__ float g_c    [B_ * J_ * NC_];
__device__ float g_cxp  [SEG_ * B_ * NC_ * M_];

// ---------- f32x2 helpers ----------
__device__ __forceinline__ unsigned long long pk2(float a, float b) {
    unsigned long long r;
    asm("mov.b64 %0, {%1,%2};" : "=l"(r) : "f"(a), "f"(b));
    return r;
}
__device__ __forceinline__ void upk2(unsigned long long v, float& a, float& b) {
    asm("mov.b64 {%0,%1}, %2;" : "=f"(a), "=f"(b) : "l"(v));
}
__device__ __forceinline__ unsigned long long ffma2(unsigned long long a,
                                                    unsigned long long b,
                                                    unsigned long long c) {
    unsigned long long d;
    asm("fma.rn.f32x2 %0, %1, %2, %3;" : "=l"(d) : "l"(a), "l"(b), "l"(c));
    return d;
}
__device__ __forceinline__ unsigned long long add2(unsigned long long a,
                                                   unsigned long long b) {
    unsigned long long d;
    asm("add.rn.f32x2 %0, %1, %2;" : "=l"(d) : "l"(a), "l"(b));
    return d;
}

// ---------- xsum partials ----------
__global__ void __launch_bounds__(256) k_xsum(const float* __restrict__ x) {
    int b = blockIdx.x, seg = blockIdx.y;
    int m = threadIdx.x;
    size_t base = ((size_t)b * J_ + seg * 128) * M_ + m;
    float s = 0.f;
#pragma unroll 8
    for (int j = 0; j < 128; ++j) s += x[base + (size_t)j * M_];
    g_xsump[((size_t)seg * B_ + b) * M_ + m] = s;
}

// ---------- caps: out = squash(row @ W_i); Wv = W_i @ out ----------
// grid (32 i, 64 b), block 256. One (b,i) per block.
template <int MODE>
__global__ void __launch_bounds__(256) k_caps(const float* __restrict__ W, float* __restrict__ out) {
    __shared__ float Wsh[M_ * 33];
    __shared__ float rowsh[M_];
    __shared__ float psh[8 * 32];
    __shared__ float osh[NC_];
    int t = threadIdx.x;
    int i = blockIdx.x, b = blockIdx.y;

#pragma unroll
    for (int c = 0; c < 32; ++c) {
        int lin = t + 256 * c;
        int m = lin >> 5, k = lin & 31;
        Wsh[m * 33 + k] = W[m * (NC_ * DC_) + i * DC_ + k];
    }

    float r = 0.f;
    if (MODE == 0) {
#pragma unroll
        for (int s = 0; s < SEG_; ++s) r += g_xsump[((size_t)s * B_ + b) * M_ + t];
    } else {
#pragma unroll
        for (int s = 0; s < SEG_; ++s)
            r += g_cxp[(((size_t)s * B_ + b) * NC_ + i) * M_ + t];
    }
    rowsh[t] = r;
    __syncthreads();

    {
        int k = t & 31, g = t >> 5;
        float p = 0.f;
#pragma unroll
        for (int mm = 0; mm < 32; ++mm)
            p += rowsh[g * 32 + mm] * Wsh[(g * 32 + mm) * 33 + k];
        psh[g * 32 + k] = p;
    }
    __syncthreads();

    if (t < 32) {
        float s = 0.f;
#pragma unroll
        for (int g = 0; g < 8; ++g) s += psh[g * 32 + t];
        float v = (MODE == 0) ? s * (1.0f / 32.0f) : s;
        float sq = v * v;
#pragma unroll
        for (int off = 16; off; off >>= 1) sq += __shfl_xor_sync(0xffffffffu, sq, off);
        float o = v / sqrtf(sq + EPS_);
        osh[t] = o;
        if (MODE == 2) out[((size_t)b * NC_ + i) * DC_ + t] = o;
    }
    __syncthreads();

    if (MODE != 2) {
        float wv = 0.f;
#pragma unroll
        for (int k = 0; k < 32; ++k) wv += Wsh[t * 33 + k] * osh[k];
        g_Wv[((size_t)b * NC_ + i) * M_ + t] = wv;
    }
}

// ---------- logits + softmax ----------
// grid (64, 8), block 256 = 8 warps. Block tile 128 j x 32 i, K=256 in 4 chunks.
// Warp w: i-group (w&3)*8 (broadcast wv), j-half (w>>2)*64. Thread tile 2j x 8i.
__global__ void __launch_bounds__(256, 2) k_logits(const float* __restrict__ x) {
    extern __shared__ char dyn[];
    ulonglong2* wvP = (ulonglong2*)dyn;                 // [64 kq][33 pad]   33792 B
    ulonglong2* xsh = (ulonglong2*)(dyn + 33792);       // [128 j][17 pad]   34816 B
    float*      b1  = (float*)(dyn + 33792);            // reuse xsh

    int t = threadIdx.x, tx = t & 31, w = t >> 5;
    int jh = (w >> 2) * 64, i0 = (w & 3) * 8;
    int b = blockIdx.x, j0 = blockIdx.y * 128;

    // stage Wv as k-quads: wvP[kq][i]
    const float4* wv4 = (const float4*)(g_Wv + (size_t)b * NC_ * M_);
#pragma unroll
    for (int c = 0; c < 8; ++c) {
        int lin = t + 256 * c;            // 2048 float4
        int i = lin >> 6, kq = lin & 63;
        float4 v = wv4[i * 64 + kq];
        ulonglong2 p; p.x = pk2(v.x, v.y); p.y = pk2(v.z, v.w);
        wvP[kq * 33 + i] = p;
    }

    unsigned long long acc[2][8] = {};    // [jj][ii]

    for (int kc = 0; kc < 4; ++kc) {
        __syncthreads();
#pragma unroll
        for (int c = 0; c < 8; ++c) {
            int lin = t + 256 * c;        // 2048 float4
            int j = lin >> 4, mq = lin & 15;
            float4 v = *(const float4*)(x + ((size_t)b * J_ + j0 + j) * M_ + kc * 64 + mq * 4);
            ulonglong2 p; p.x = pk2(v.x, v.y); p.y = pk2(v.z, v.w);
            xsh[j * 17 + mq] = p;
        }
        __syncthreads();
#pragma unroll 4
        for (int kq = 0; kq < 16; ++kq) {
            ulonglong2 xv[2], wv[8];
#pragma unroll
            for (int jj = 0; jj < 2; ++jj) xv[jj] = xsh[(jh + tx + 32 * jj) * 17 + kq];
#pragma unroll
            for (int ii = 0; ii < 8; ++ii) wv[ii] = wvP[(kc * 16 + kq) * 33 + i0 + ii];
#pragma unroll
            for (int jj = 0; jj < 2; ++jj)
#pragma unroll
                for (int ii = 0; ii < 8; ++ii)
                    acc[jj][ii] = ffma2(xv[jj].y, wv[ii].y,
                                  ffma2(xv[jj].x, wv[ii].x, acc[jj][ii]));
        }
    }
    __syncthreads();                      // xsh reads done; reuse as b1
#pragma unroll
    for (int jj = 0; jj < 2; ++jj)
#pragma unroll
        for (int ii = 0; ii < 8; ++ii) {
            float lo, hi; upk2(acc[jj][ii], lo, hi);
            b1[(jh + tx + 32 * jj) * 33 + i0 + ii] = lo + hi;
        }
    __syncthreads();

    if (t < 128) {                        // softmax over i per j
        float* row = b1 + t * 33;
        float mx = row[0];
#pragma unroll
        for (int i = 1; i < 32; ++i) mx = fmaxf(mx, row[i]);
        float s = 0.f;
#pragma unroll
        for (int i = 0; i < 32; ++i) { float e = __expf(row[i] - mx); row[i] = e; s += e; }
        float inv = 1.0f / s;
        float* cg = g_c + ((size_t)b * J_ + j0 + t) * NC_;
#pragma unroll
        for (int q = 0; q < 8; ++q) {
            float4 o;
            o.x = row[4 * q + 0] * inv; o.y = row[4 * q + 1] * inv;
            o.z = row[4 * q + 2] * inv; o.w = row[4 * q + 3] * inv;
            ((float4*)cg)[q] = o;
        }
    }
}

// ---------- cx partials ----------
// grid (64, 8), block 256 = 8 warps. Warp w: i-group (w&3)*8, j-half h = w>>2.
// Thread tile 8i x 4m2 (32 FMA2 per j). In-block pair-sum, 8 output slabs.
__global__ void __launch_bounds__(256, 2) k_cx(const float* __restrict__ x) {
    __shared__ ulonglong2 xsh[32 * 64];   // [32 j][64 ull2 = 128 m2]  32 KB
    __shared__ float      csh[32 * 32];   // [32 j][32 i]               4 KB
    int t = threadIdx.x, tx = t & 31, w = t >> 5;
    int h = w >> 2, i0 = (w & 3) * 8;
    int b = blockIdx.x, seg = blockIdx.y, j0 = seg * 128;

    const unsigned long long* xshu = (const unsigned long long*)xsh;
    const float4* csh4 = (const float4*)csh;

    unsigned long long acc[8][4] = {};    // [ii][mm]

    for (int jc = 0; jc < 4; ++jc) {
        __syncthreads();
        int jb = j0 + jc * 32;
#pragma unroll
        for (int c = 0; c < 8; ++c) {
            int lin = t + 256 * c;        // 2048 float4
            int j = lin >> 6, mq = lin & 63;
            float4 v = *(const float4*)(x + ((size_t)b * J_ + jb + j) * M_ + mq * 4);
            ulonglong2 p; p.x = pk2(v.x, v.y); p.y = pk2(v.z, v.w);
            xsh[j * 64 + mq] = p;
        }
        {
            int j = t >> 3, q = t & 7;    // 256 float4 = full c tile
            float4 v = *(const float4*)(g_c + ((size_t)b * J_ + jb + j) * NC_ + q * 4);
            ((float4*)csh)[j * 8 + q] = v;
        }
        __syncthreads();
#pragma unroll 4
        for (int jl = 0; jl < 16; ++jl) {
            int j = h * 16 + jl;
            float4 ca = csh4[j * 8 + (w & 3) * 2];
            float4 cb = csh4[j * 8 + (w & 3) * 2 + 1];
            unsigned long long cc[8];
            cc[0] = pk2(ca.x, ca.x); cc[1] = pk2(ca.y, ca.y);
            cc[2] = pk2(ca.z, ca.z); cc[3] = pk2(ca.w, ca.w);
            cc[4] = pk2(cb.x, cb.x); cc[5] = pk2(cb.y, cb.y);
            cc[6] = pk2(cb.z, cb.z); cc[7] = pk2(cb.w, cb.w);
            unsigned long long xv[4];
#pragma unroll
            for (int mm = 0; mm < 4; ++mm) xv[mm] = xshu[j * 128 + tx + 32 * mm];
#pragma unroll
            for (int ii = 0; ii < 8; ++ii)
#pragma unroll
                for (int mm = 0; mm < 4; ++mm)
                    acc[ii][mm] = ffma2(xv[mm], cc[ii], acc[ii][mm]);
        }
    }

    // pair-sum: warps 4-7 hand off to warps 0-3 (same i-group) via smem
    __syncthreads();
    unsigned long long* exu = (unsigned long long*)xsh;   // 4096 ull = 32 KB, exact
    if (w >= 4) {
        int lane = t - 128;               // 0..127
#pragma unroll
        for (int k = 0; k < 32; ++k)
            exu[k * 128 + lane] = acc[k >> 2][k & 3];
    }
    __syncthreads();
    if (w < 4) {
#pragma unroll
        for (int k = 0; k < 32; ++k)
            acc[k >> 2][k & 3] = add2(acc[k >> 2][k & 3], exu[k * 128 + t]);
#pragma unroll
        for (int ii = 0; ii < 8; ++ii)
#pragma unroll
            for (int mm = 0; mm < 4; ++mm) {
                float lo, hi; upk2(acc[ii][mm], lo, hi);
                size_t o = (((size_t)seg * B_ + b) * NC_ + i0 + ii) * M_ + 2 * (tx + 32 * mm);
                float2 v; v.x = lo; v.y = hi;
                *(float2*)(g_cxp + o) = v;
            }
    }
}

extern "C" void kernel_launch(void* const* d_in, const int* in_sizes, int n_in,
                              void* d_out, int out_size) {
    const float* x = (const float*)d_in[0];
    const float* W = (const float*)d_in[1];
    if (n_in >= 2 && in_sizes[0] < in_sizes[1]) {
        const float* tmp = x; x = W; W = tmp;
    }
    float* out = (float*)d_out;

    cudaFuncSetAttribute(k_logits, cudaFuncAttributeMaxDynamicSharedMemorySize, 68608);

    k_xsum<<<dim3(B_, SEG_), 256>>>(x);
    k_caps<0><<<dim3(NC_, B_), 256>>>(W, out);

    k_logits<<<dim3(B_, SEG_), 256, 68608>>>(x);
    k_cx<<<dim3(B_, SEG_), 256>>>(x);
    k_caps<1><<<dim3(NC_, B_), 256>>>(W, out);

    k_logits<<<dim3(B_, SEG_), 256, 68608>>>(x);
    k_cx<<<dim3(B_, SEG_), 256>>>(x);
    k_caps<2><<<dim3(NC_, B_), 256>>>(W, out);
}

// round 7
// speedup vs baseline: 1.1546x; 1.0325x over previous
#include <cuda_runtime.h>
#include <cstdint>

#define B_    64
#define J_    1024
#define M_    256
#define NC_   32
#define DC_   32
#define EPS_  1e-7f
#define SEG_  8

// Scratch
__device__ float g_xsump[SEG_ * B_ * M_];
__device__ float g_Wv   [B_ * NC_ * M_];
__device__ float g_c    [B_ * J_ * NC_];
__device__ float g_cxp  [SEG_ * B_ * NC_ * M_];

// ---------- f32x2 helpers ----------
__device__ __forceinline__ unsigned long long pk2(float a, float b) {
    unsigned long long r;
    asm("mov.b64 %0, {%1,%2};" : "=l"(r) : "f"(a), "f"(b));
    return r;
}
__device__ __forceinline__ void upk2(unsigned long long v, float& a, float& b) {
    asm("mov.b64 {%0,%1}, %2;" : "=f"(a), "=f"(b) : "l"(v));
}
__device__ __forceinline__ unsigned long long ffma2(unsigned long long a,
                                                    unsigned long long b,
                                                    unsigned long long c) {
    unsigned long long d;
    asm("fma.rn.f32x2 %0, %1, %2, %3;" : "=l"(d) : "l"(a), "l"(b), "l"(c));
    return d;
}
__device__ __forceinline__ unsigned long long add2(unsigned long long a,
                                                   unsigned long long b) {
    unsigned long long d;
    asm("add.rn.f32x2 %0, %1, %2;" : "=l"(d) : "l"(a), "l"(b));
    return d;
}

// ---------- xsum partials ----------
__global__ void __launch_bounds__(256) k_xsum(const float* __restrict__ x) {
    int b = blockIdx.x, seg = blockIdx.y;
    int m = threadIdx.x;
    size_t base = ((size_t)b * J_ + seg * 128) * M_ + m;
    float s = 0.f;
#pragma unroll 8
    for (int j = 0; j < 128; ++j) s += x[base + (size_t)j * M_];
    g_xsump[((size_t)seg * B_ + b) * M_ + m] = s;
}

// ---------- caps: out = squash(row @ W_i); Wv = W_i @ out ----------
// grid (32 i, 64 b), block 256. One (b,i) per block.
template <int MODE>
__global__ void __launch_bounds__(256) k_caps(const float* __restrict__ W, float* __restrict__ out) {
    __shared__ float Wsh[M_ * 33];
    __shared__ float rowsh[M_];
    __shared__ float psh[8 * 32];
    __shared__ float osh[NC_];
    int t = threadIdx.x;
    int i = blockIdx.x, b = blockIdx.y;

#pragma unroll
    for (int c = 0; c < 32; ++c) {
        int lin = t + 256 * c;
        int m = lin >> 5, k = lin & 31;
        Wsh[m * 33 + k] = W[m * (NC_ * DC_) + i * DC_ + k];
    }

    float r = 0.f;
    if (MODE == 0) {
#pragma unroll
        for (int s = 0; s < SEG_; ++s) r += g_xsump[((size_t)s * B_ + b) * M_ + t];
    } else {
#pragma unroll
        for (int s = 0; s < SEG_; ++s)
            r += g_cxp[(((size_t)s * B_ + b) * NC_ + i) * M_ + t];
    }
    rowsh[t] = r;
    __syncthreads();

    {
        int k = t & 31, g = t >> 5;
        float p = 0.f;
#pragma unroll
        for (int mm = 0; mm < 32; ++mm)
            p += rowsh[g * 32 + mm] * Wsh[(g * 32 + mm) * 33 + k];
        psh[g * 32 + k] = p;
    }
    __syncthreads();

    if (t < 32) {
        float s = 0.f;
#pragma unroll
        for (int g = 0; g < 8; ++g) s += psh[g * 32 + t];
        float v = (MODE == 0) ? s * (1.0f / 32.0f) : s;
        float sq = v * v;
#pragma unroll
        for (int off = 16; off; off >>= 1) sq += __shfl_xor_sync(0xffffffffu, sq, off);
        float o = v / sqrtf(sq + EPS_);
        osh[t] = o;
        if (MODE == 2) out[((size_t)b * NC_ + i) * DC_ + t] = o;
    }
    __syncthreads();

    if (MODE != 2) {
        float wv = 0.f;
#pragma unroll
        for (int k = 0; k < 32; ++k) wv += Wsh[t * 33 + k] * osh[k];
        g_Wv[((size_t)b * NC_ + i) * M_ + t] = wv;
    }
}

// ---------- logits + softmax ----------
// grid (64, 8), block 256 = 8 warps. Block tile 128 j x 32 i, K=256 in 4 chunks.
// Warp w: i-group (w&3)*8 (broadcast wv), j-half (w>>2)*64. Thread tile 2j x 8i.
__global__ void __launch_bounds__(256, 2) k_logits(const float* __restrict__ x) {
    extern __shared__ char dyn[];
    ulonglong2* wvP = (ulonglong2*)dyn;                 // [64 kq][33 pad]   33792 B
    ulonglong2* xsh = (ulonglong2*)(dyn + 33792);       // [128 j][17 pad]   34816 B
    float*      b1  = (float*)(dyn + 33792);            // reuse xsh

    int t = threadIdx.x, tx = t & 31, w = t >> 5;
    int jh = (w >> 2) * 64, i0 = (w & 3) * 8;
    int b = blockIdx.x, j0 = blockIdx.y * 128;

    // stage Wv as k-quads: wvP[kq][i]
    const float4* wv4 = (const float4*)(g_Wv + (size_t)b * NC_ * M_);
#pragma unroll
    for (int c = 0; c < 8; ++c) {
        int lin = t + 256 * c;            // 2048 float4
        int i = lin >> 6, kq = lin & 63;
        float4 v = wv4[i * 64 + kq];
        ulonglong2 p; p.x = pk2(v.x, v.y); p.y = pk2(v.z, v.w);
        wvP[kq * 33 + i] = p;
    }

    unsigned long long acc[2][8] = {};    // [jj][ii]

    for (int kc = 0; kc < 4; ++kc) {
        __syncthreads();
#pragma unroll
        for (int c = 0; c < 8; ++c) {
            int lin = t + 256 * c;        // 2048 float4
            int j = lin >> 4, mq = lin & 15;
            float4 v = *(const float4*)(x + ((size_t)b * J_ + j0 + j) * M_ + kc * 64 + mq * 4);
            ulonglong2 p; p.x = pk2(v.x, v.y); p.y = pk2(v.z, v.w);
            xsh[j * 17 + mq] = p;
        }
        __syncthreads();
#pragma unroll 4
        for (int kq = 0; kq < 16; ++kq) {
            ulonglong2 xv[2], wv[8];
#pragma unroll
            for (int jj = 0; jj < 2; ++jj) xv[jj] = xsh[(jh + tx + 32 * jj) * 17 + kq];
#pragma unroll
            for (int ii = 0; ii < 8; ++ii) wv[ii] = wvP[(kc * 16 + kq) * 33 + i0 + ii];
#pragma unroll
            for (int jj = 0; jj < 2; ++jj)
#pragma unroll
                for (int ii = 0; ii < 8; ++ii)
                    acc[jj][ii] = ffma2(xv[jj].y, wv[ii].y,
                                  ffma2(xv[jj].x, wv[ii].x, acc[jj][ii]));
        }
    }
    __syncthreads();                      // xsh reads done; reuse as b1
#pragma unroll
    for (int jj = 0; jj < 2; ++jj)
#pragma unroll
        for (int ii = 0; ii < 8; ++ii) {
            float lo, hi; upk2(acc[jj][ii], lo, hi);
            b1[(jh + tx + 32 * jj) * 33 + i0 + ii] = lo + hi;
        }
    __syncthreads();

    if (t < 128) {                        // softmax over i per j
        float* row = b1 + t * 33;
        float mx = row[0];
#pragma unroll
        for (int i = 1; i < 32; ++i) mx = fmaxf(mx, row[i]);
        float s = 0.f;
#pragma unroll
        for (int i = 0; i < 32; ++i) { float e = __expf(row[i] - mx); row[i] = e; s += e; }
        float inv = 1.0f / s;
        float* cg = g_c + ((size_t)b * J_ + j0 + t) * NC_;
#pragma unroll
        for (int q = 0; q < 8; ++q) {
            float4 o;
            o.x = row[4 * q + 0] * inv; o.y = row[4 * q + 1] * inv;
            o.z = row[4 * q + 2] * inv; o.w = row[4 * q + 3] * inv;
            ((float4*)cg)[q] = o;
        }
    }
}

// ---------- cx partials ----------
// grid (64, 8), block 256 = 8 warps. Warp w: i-group (w&3)*8, j-half h = w>>2.
// Thread tile 8i x 4m2 (32 FMA2 per j). In-block pair-sum, 8 output slabs.
__global__ void __launch_bounds__(256, 2) k_cx(const float* __restrict__ x) {
    __shared__ ulonglong2 xsh[32 * 64];   // [32 j][64 ull2 = 128 m2]  32 KB
    __shared__ float      csh[32 * 32];   // [32 j][32 i]               4 KB
    int t = threadIdx.x, tx = t & 31, w = t >> 5;
    int h = w >> 2, i0 = (w & 3) * 8;
    int b = blockIdx.x, seg = blockIdx.y, j0 = seg * 128;

    const unsigned long long* xshu = (const unsigned long long*)xsh;
    const float4* csh4 = (const float4*)csh;

    unsigned long long acc[8][4] = {};    // [ii][mm]

    for (int jc = 0; jc < 4; ++jc) {
        __syncthreads();
        int jb = j0 + jc * 32;
#pragma unroll
        for (int c = 0; c < 8; ++c) {
            int lin = t + 256 * c;        // 2048 float4
            int j = lin >> 6, mq = lin & 63;
            float4 v = *(const float4*)(x + ((size_t)b * J_ + jb + j) * M_ + mq * 4);
            ulonglong2 p; p.x = pk2(v.x, v.y); p.y = pk2(v.z, v.w);
            xsh[j * 64 + mq] = p;
        }
        {
            int j = t >> 3, q = t & 7;    // 256 float4 = full c tile
            float4 v = *(const float4*)(g_c + ((size_t)b * J_ + jb + j) * NC_ + q * 4);
            ((float4*)csh)[j * 8 + q] = v;
        }
        __syncthreads();
#pragma unroll 4
        for (int jl = 0; jl < 16; ++jl) {
            int j = h * 16 + jl;
            float4 ca = csh4[j * 8 + (w & 3) * 2];
            float4 cb = csh4[j * 8 + (w & 3) * 2 + 1];
            unsigned long long cc[8];
            cc[0] = pk2(ca.x, ca.x); cc[1] = pk2(ca.y, ca.y);
            cc[2] = pk2(ca.z, ca.z); cc[3] = pk2(ca.w, ca.w);
            cc[4] = pk2(cb.x, cb.x); cc[5] = pk2(cb.y, cb.y);
            cc[6] = pk2(cb.z, cb.z); cc[7] = pk2(cb.w, cb.w);
            unsigned long long xv[4];
#pragma unroll
            for (int mm = 0; mm < 4; ++mm) xv[mm] = xshu[j * 128 + tx + 32 * mm];
#pragma unroll
            for (int ii = 0; ii < 8; ++ii)
#pragma unroll
                for (int mm = 0; mm < 4; ++mm)
                    acc[ii][mm] = ffma2(xv[mm], cc[ii], acc[ii][mm]);
        }
    }

    // pair-sum: warps 4-7 hand off to warps 0-3 (same i-group) via smem
    __syncthreads();
    unsigned long long* exu = (unsigned long long*)xsh;   // 4096 ull = 32 KB, exact
    if (w >= 4) {
        int lane = t - 128;               // 0..127
#pragma unroll
        for (int k = 0; k < 32; ++k)
            exu[k * 128 + lane] = acc[k >> 2][k & 3];
    }
    __syncthreads();
    if (w < 4) {
#pragma unroll
        for (int k = 0; k < 32; ++k)
            acc[k >> 2][k & 3] = add2(acc[k >> 2][k & 3], exu[k * 128 + t]);
#pragma unroll
        for (int ii = 0; ii < 8; ++ii)
#pragma unroll
            for (int mm = 0; mm < 4; ++mm) {
                float lo, hi; upk2(acc[ii][mm], lo, hi);
                size_t o = (((size_t)seg * B_ + b) * NC_ + i0 + ii) * M_ + 2 * (tx + 32 * mm);
                float2 v; v.x = lo; v.y = hi;
                *(float2*)(g_cxp + o) = v;
            }
    }
}

extern "C" void kernel_launch(void* const* d_in, const int* in_sizes, int n_in,
                              void* d_out, int out_size) {
    const float* x = (const float*)d_in[0];
    const float* W = (const float*)d_in[1];
    if (n_in >= 2 && in_sizes[0] < in_sizes[1]) {
        const float* tmp = x; x = W; W = tmp;
    }
    float* out = (float*)d_out;

    cudaFuncSetAttribute(k_logits, cudaFuncAttributeMaxDynamicSharedMemorySize, 68608);

    k_xsum<<<dim3(B_, SEG_), 256>>>(x);
    k_caps<0><<<dim3(NC_, B_), 256>>>(W, out);

    k_logits<<<dim3(B_, SEG_), 256, 68608>>>(x);
    k_cx<<<dim3(B_, SEG_), 256>>>(x);
    k_caps<1><<<dim3(NC_, B_), 256>>>(W, out);

    k_logits<<<dim3(B_, SEG_), 256, 68608>>>(x);
    k_cx<<<dim3(B_, SEG_), 256>>>(x);
    k_caps<2><<<dim3(NC_, B_), 256>>>(W, out);
}

// round 8
// speedup vs baseline: 1.3635x; 1.1810x over previous
#include <cuda_runtime.h>
#include <cuda_fp16.h>
#include <cstdint>

#define B_    64
#define J_    1024
#define M_    256
#define NC_   32
#define DC_   32
#define EPS_  1e-7f
#define SEG_  8

// Scratch
__device__ float  g_xsump[SEG_ * B_ * M_];
__device__ float  g_Wv   [B_ * NC_ * M_];
__device__ float  g_cxp  [SEG_ * B_ * NC_ * M_];
__device__ __half g_ch   [B_ * NC_ * J_];    // c hi plane, [b][i][j]
__device__ __half g_cl   [B_ * NC_ * J_];    // c lo plane (x4096)

// ---------- helpers ----------
__device__ __forceinline__ void splitf(float f, __half& h, __half& l) {
    h = __float2half_rn(f);
    l = __float2half_rn((f - __half2float(h)) * 4096.0f);
}

__device__ __forceinline__ void mma16816(float& c0, float& c1, float& c2, float& c3,
                                         uint32_t a0, uint32_t a1, uint32_t a2, uint32_t a3,
                                         uint32_t b0, uint32_t b1) {
    asm volatile(
        "mma.sync.aligned.m16n8k16.row.col.f32.f16.f16.f32 "
        "{%0,%1,%2,%3}, {%4,%5,%6,%7}, {%8,%9}, {%0,%1,%2,%3};"
        : "+f"(c0), "+f"(c1), "+f"(c2), "+f"(c3)
        : "r"(a0), "r"(a1), "r"(a2), "r"(a3), "r"(b0), "r"(b1));
}

// ---------- xsum partials ----------
__global__ void __launch_bounds__(256) k_xsum(const float* __restrict__ x) {
    int b = blockIdx.x, seg = blockIdx.y;
    int m = threadIdx.x;
    size_t base = ((size_t)b * J_ + seg * 128) * M_ + m;
    float s = 0.f;
#pragma unroll 8
    for (int j = 0; j < 128; ++j) s += x[base + (size_t)j * M_];
    g_xsump[((size_t)seg * B_ + b) * M_ + m] = s;
}

// ---------- caps: out = squash(row @ W_i); Wv = W_i @ out ----------
// grid (32 i, 8 bg), block 256; W_i staged once, 8 batches per block.
template <int MODE>
__global__ void __launch_bounds__(256) k_caps(const float* __restrict__ W, float* __restrict__ out) {
    __shared__ float Wsh[M_ * 33];
    __shared__ float rowsh[M_];
    __shared__ float psh[8 * 32];
    __shared__ float osh[NC_];
    int t = threadIdx.x;
    int i = blockIdx.x, bg = blockIdx.y;

#pragma unroll
    for (int c = 0; c < 32; ++c) {
        int lin = t + 256 * c;
        int m = lin >> 5, k = lin & 31;
        Wsh[m * 33 + k] = W[m * (NC_ * DC_) + i * DC_ + k];
    }

    for (int bb = 0; bb < 8; ++bb) {
        int b = bg * 8 + bb;
        float r = 0.f;
        if (MODE == 0) {
#pragma unroll
            for (int s = 0; s < SEG_; ++s) r += g_xsump[((size_t)s * B_ + b) * M_ + t];
        } else {
#pragma unroll
            for (int s = 0; s < SEG_; ++s)
                r += g_cxp[(((size_t)s * B_ + b) * NC_ + i) * M_ + t];
        }
        __syncthreads();
        rowsh[t] = r;
        __syncthreads();

        {
            int k = t & 31, g = t >> 5;
            float p = 0.f;
#pragma unroll
            for (int mm = 0; mm < 32; ++mm)
                p += rowsh[g * 32 + mm] * Wsh[(g * 32 + mm) * 33 + k];
            psh[g * 32 + k] = p;
        }
        __syncthreads();

        if (t < 32) {
            float s = 0.f;
#pragma unroll
            for (int g = 0; g < 8; ++g) s += psh[g * 32 + t];
            float v = (MODE == 0) ? s * (1.0f / 32.0f) : s;
            float sq = v * v;
#pragma unroll
            for (int off = 16; off; off >>= 1) sq += __shfl_xor_sync(0xffffffffu, sq, off);
            float o = v / sqrtf(sq + EPS_);
            osh[t] = o;
            if (MODE == 2) out[((size_t)b * NC_ + i) * DC_ + t] = o;
        }
        __syncthreads();

        if (MODE != 2) {
            float wv = 0.f;
#pragma unroll
            for (int k = 0; k < 32; ++k) wv += Wsh[t * 33 + k] * osh[k];
            g_Wv[((size_t)b * NC_ + i) * M_ + t] = wv;
        }
        __syncthreads();
    }
}

// ---------- logits + softmax (tensor core) ----------
// grid (64, 8), block 256 = 8 warps. Block tile 128 j x 32 i, K = 256 m.
// Warp w = j-tile w (16 j); all 4 i-tiles (n=8 each). mma m16n8k16 fp16 hi/lo.
// smem (halves): WH[32][264] @0, WL @8448, XH[128][72] @16896, XL @26112.
__global__ void __launch_bounds__(256, 2) k_logits(const float* __restrict__ x) {
    extern __shared__ __half sm[];
    __half* WH = sm;
    __half* WL = sm + 8448;
    __half* XH = sm + 16896;
    __half* XL = sm + 26112;
    float*  b1 = (float*)(sm + 16896);   // [128][33], reuses XH/XL after mainloop

    int t = threadIdx.x, lane = t & 31, w = t >> 5;
    int g = lane >> 2, tig = lane & 3;
    int b = blockIdx.x, j0 = blockIdx.y * 128;

    // stage Wv hi/lo: WH[i][m]
    const float4* wv4 = (const float4*)(g_Wv + (size_t)b * NC_ * M_);
#pragma unroll
    for (int c = 0; c < 8; ++c) {
        int lin = t + 256 * c;           // 2048 float4
        int i = lin >> 6, mq = lin & 63;
        float4 v = wv4[i * 64 + mq];
        __half h0, l0, h1, l1, h2, l2, h3, l3;
        splitf(v.x, h0, l0); splitf(v.y, h1, l1);
        splitf(v.z, h2, l2); splitf(v.w, h3, l3);
        int o = i * 264 + mq * 4;
        *(__half2*)(WH + o)     = __halves2half2(h0, h1);
        *(__half2*)(WH + o + 2) = __halves2half2(h2, h3);
        *(__half2*)(WL + o)     = __halves2half2(l0, l1);
        *(__half2*)(WL + o + 2) = __halves2half2(l2, l3);
    }

    float hh[4][4], lo[4][4];
#pragma unroll
    for (int nt = 0; nt < 4; ++nt)
#pragma unroll
        for (int q = 0; q < 4; ++q) { hh[nt][q] = 0.f; lo[nt][q] = 0.f; }

    for (int kc = 0; kc < 4; ++kc) {     // m-chunks of 64
        __syncthreads();
#pragma unroll
        for (int c = 0; c < 8; ++c) {
            int lin = t + 256 * c;       // 2048 float4
            int j = lin >> 4, mq = lin & 15;
            float4 v = *(const float4*)(x + ((size_t)b * J_ + j0 + j) * M_ + kc * 64 + mq * 4);
            __half h0, l0, h1, l1, h2, l2, h3, l3;
            splitf(v.x, h0, l0); splitf(v.y, h1, l1);
            splitf(v.z, h2, l2); splitf(v.w, h3, l3);
            int o = j * 72 + mq * 4;
            *(__half2*)(XH + o)     = __halves2half2(h0, h1);
            *(__half2*)(XH + o + 2) = __halves2half2(h2, h3);
            *(__half2*)(XL + o)     = __halves2half2(l0, l1);
            *(__half2*)(XL + o + 2) = __halves2half2(l2, l3);
        }
        __syncthreads();

        const uint32_t* XH2 = (const uint32_t*)XH;
        const uint32_t* XL2 = (const uint32_t*)XL;
        const uint32_t* WH2 = (const uint32_t*)WH;
        const uint32_t* WL2 = (const uint32_t*)WL;
#pragma unroll
        for (int ks = 0; ks < 4; ++ks) { // k16 steps within chunk
            int ab = (w * 16 + g) * 36 + ks * 8 + tig;
            uint32_t ah0 = XH2[ab],           ah1 = XH2[ab + 288];
            uint32_t ah2 = XH2[ab + 4],       ah3 = XH2[ab + 292];
            uint32_t al0 = XL2[ab],           al1 = XL2[ab + 288];
            uint32_t al2 = XL2[ab + 4],       al3 = XL2[ab + 292];
            int km = kc * 32 + ks * 8;       // word offset into WH rows
#pragma unroll
            for (int nt = 0; nt < 4; ++nt) {
                int bb = (nt * 8 + g) * 132 + km + tig;
                uint32_t bh0 = WH2[bb], bh1 = WH2[bb + 4];
                uint32_t bl0 = WL2[bb], bl1 = WL2[bb + 4];
                mma16816(hh[nt][0], hh[nt][1], hh[nt][2], hh[nt][3],
                         ah0, ah1, ah2, ah3, bh0, bh1);
                mma16816(lo[nt][0], lo[nt][1], lo[nt][2], lo[nt][3],
                         al0, al1, al2, al3, bh0, bh1);
                mma16816(lo[nt][0], lo[nt][1], lo[nt][2], lo[nt][3],
                         ah0, ah1, ah2, ah3, bl0, bl1);
            }
        }
    }
    __syncthreads();

    // combine + write logits to b1[j][i]
#pragma unroll
    for (int nt = 0; nt < 4; ++nt) {
        int col = nt * 8 + 2 * tig;
        int row = w * 16 + g;
        b1[row * 33 + col]           = hh[nt][0] + lo[nt][0] * (1.0f / 4096.0f);
        b1[row * 33 + col + 1]       = hh[nt][1] + lo[nt][1] * (1.0f / 4096.0f);
        b1[(row + 8) * 33 + col]     = hh[nt][2] + lo[nt][2] * (1.0f / 4096.0f);
        b1[(row + 8) * 33 + col + 1] = hh[nt][3] + lo[nt][3] * (1.0f / 4096.0f);
    }
    __syncthreads();

    if (t < 128) {                       // softmax over i per j; write c hi/lo planes
        float* row = b1 + t * 33;
        float mx = row[0];
#pragma unroll
        for (int i = 1; i < 32; ++i) mx = fmaxf(mx, row[i]);
        float s = 0.f;
        float e[32];
#pragma unroll
        for (int i = 0; i < 32; ++i) { e[i] = __expf(row[i] - mx); s += e[i]; }
        float inv = 1.0f / s;
        size_t cbase = (size_t)b * NC_ * J_ + (size_t)(j0 + t);
#pragma unroll
        for (int i = 0; i < 32; ++i) {
            __half h, l;
            splitf(e[i] * inv, h, l);
            g_ch[cbase + (size_t)i * J_] = h;
            g_cl[cbase + (size_t)i * J_] = l;
        }
    }
}

// ---------- cx partials (tensor core) ----------
// grid (64 b, 8 seg), block 256 = 8 warps. cx[i,m] = sum_j c[j,i] x[j,m].
// A = cT (i x j, row-major), B = x (k=j x n=m, col-major as XT[m][j]).
// Warp w: m-cols w*32..w*32+31 (4 n-tiles); both i-tiles. K = 128 j in 4 chunks of 32.
__global__ void __launch_bounds__(256) k_cx(const float* __restrict__ x) {
    __shared__ __half XT[2][256 * 40];   // [plane][m][j-pad40]
    __shared__ __half CT[2][32 * 40];    // [plane][i][j-pad40]

    int t = threadIdx.x, lane = t & 31, w = t >> 5;
    int g = lane >> 2, tig = lane & 3;
    int b = blockIdx.x, seg = blockIdx.y;

    float hh[2][4][4], lo[2][4][4];
#pragma unroll
    for (int it = 0; it < 2; ++it)
#pragma unroll
        for (int nt = 0; nt < 4; ++nt)
#pragma unroll
            for (int q = 0; q < 4; ++q) { hh[it][nt][q] = 0.f; lo[it][nt][q] = 0.f; }

    for (int jc = 0; jc < 4; ++jc) {     // j-chunks of 32
        __syncthreads();
        int jb = seg * 128 + jc * 32;
        // stage x transposed hi/lo: XT[plane][m][j]
#pragma unroll
        for (int c = 0; c < 8; ++c) {
            int lin = t + 256 * c;       // 2048 float4
            int j = lin & 31, mq = lin >> 5;
            float4 v = *(const float4*)(x + ((size_t)b * J_ + jb + j) * M_ + mq * 4);
            __half h, l;
            splitf(v.x, h, l); XT[0][(mq * 4 + 0) * 40 + j] = h; XT[1][(mq * 4 + 0) * 40 + j] = l;
            splitf(v.y, h, l); XT[0][(mq * 4 + 1) * 40 + j] = h; XT[1][(mq * 4 + 1) * 40 + j] = l;
            splitf(v.z, h, l); XT[0][(mq * 4 + 2) * 40 + j] = h; XT[1][(mq * 4 + 2) * 40 + j] = l;
            splitf(v.w, h, l); XT[0][(mq * 4 + 3) * 40 + j] = h; XT[1][(mq * 4 + 3) * 40 + j] = l;
        }
        // stage c hi/lo: CT[plane][i][j]
#pragma unroll
        for (int cc = 0; cc < 2; ++cc) {
            int idx = t + 256 * cc;      // 512 half2 per plane
            int i = idx >> 4, j2 = idx & 15;
            size_t srco = (size_t)(b * NC_ + i) * (J_ / 2) + (size_t)(seg * 64 + jc * 16) + j2;
            ((__half2*)CT[0])[i * 20 + j2] = ((const __half2*)g_ch)[srco];
            ((__half2*)CT[1])[i * 20 + j2] = ((const __half2*)g_cl)[srco];
        }
        __syncthreads();

        const uint32_t* XTH = (const uint32_t*)XT[0];
        const uint32_t* XTL = (const uint32_t*)XT[1];
        const uint32_t* CTH = (const uint32_t*)CT[0];
        const uint32_t* CTL = (const uint32_t*)CT[1];
#pragma unroll
        for (int ks = 0; ks < 2; ++ks) { // 2 k16-steps per chunk
            int k0w = ks * 8;
            uint32_t ah[2][4], al[2][4];
#pragma unroll
            for (int it = 0; it < 2; ++it) {
                int ab = (it * 16 + g) * 20 + k0w + tig;
                ah[it][0] = CTH[ab];       ah[it][1] = CTH[ab + 160];
                ah[it][2] = CTH[ab + 4];   ah[it][3] = CTH[ab + 164];
                al[it][0] = CTL[ab];       al[it][1] = CTL[ab + 160];
                al[it][2] = CTL[ab + 4];   al[it][3] = CTL[ab + 164];
            }
#pragma unroll
            for (int nt = 0; nt < 4; ++nt) {
                int col = w * 32 + nt * 8 + g;
                int bb = col * 20 + k0w + tig;
                uint32_t bh0 = XTH[bb], bh1 = XTH[bb + 4];
                uint32_t bl0 = XTL[bb], bl1 = XTL[bb + 4];
#pragma unroll
                for (int it = 0; it < 2; ++it) {
                    mma16816(hh[it][nt][0], hh[it][nt][1], hh[it][nt][2], hh[it][nt][3],
                             ah[it][0], ah[it][1], ah[it][2], ah[it][3], bh0, bh1);
                    mma16816(lo[it][nt][0], lo[it][nt][1], lo[it][nt][2], lo[it][nt][3],
                             al[it][0], al[it][1], al[it][2], al[it][3], bh0, bh1);
                    mma16816(lo[it][nt][0], lo[it][nt][1], lo[it][nt][2], lo[it][nt][3],
                             ah[it][0], ah[it][1], ah[it][2], ah[it][3], bl0, bl1);
                }
            }
        }
    }

    // combine + write fp32 partial slab
#pragma unroll
    for (int it = 0; it < 2; ++it)
#pragma unroll
        for (int nt = 0; nt < 4; ++nt) {
            int i = it * 16 + g;
            int m = w * 32 + nt * 8 + 2 * tig;
            size_t base = (((size_t)seg * B_ + b) * NC_ + i) * M_ + m;
            float2 v0, v1;
            v0.x = hh[it][nt][0] + lo[it][nt][0] * (1.0f / 4096.0f);
            v0.y = hh[it][nt][1] + lo[it][nt][1] * (1.0f / 4096.0f);
            v1.x = hh[it][nt][2] + lo[it][nt][2] * (1.0f / 4096.0f);
            v1.y = hh[it][nt][3] + lo[it][nt][3] * (1.0f / 4096.0f);
            *(float2*)(g_cxp + base)            = v0;
            *(float2*)(g_cxp + base + 8 * M_)   = v1;
        }
}

extern "C" void kernel_launch(void* const* d_in, const int* in_sizes, int n_in,
                              void* d_out, int out_size) {
    const float* x = (const float*)d_in[0];
    const float* W = (const float*)d_in[1];
    if (n_in >= 2 && in_sizes[0] < in_sizes[1]) {
        const float* tmp = x; x = W; W = tmp;
    }
    float* out = (float*)d_out;

    cudaFuncSetAttribute(k_logits, cudaFuncAttributeMaxDynamicSharedMemorySize, 70656);

    k_xsum<<<dim3(B_, SEG_), 256>>>(x);
    k_caps<0><<<dim3(NC_, 8), 256>>>(W, out);

    k_logits<<<dim3(B_, SEG_), 256, 70656>>>(x);
    k_cx<<<dim3(B_, SEG_), 256>>>(x);
    k_caps<1><<<dim3(NC_, 8), 256>>>(W, out);

    k_logits<<<dim3(B_, SEG_), 256, 70656>>>(x);
    k_cx<<<dim3(B_, SEG_), 256>>>(x);
    k_caps<2><<<dim3(NC_, 8), 256>>>(W, out);
}